// round 1
// baseline (speedup 1.0000x reference)
#include <cuda_runtime.h>

#define N 384
#define D 256
#define EPSF 1e-12f

// scratch (no allocation allowed)
__device__ float  g_Gs[N * N];
__device__ float  g_Gt[N * N];
__device__ float  g_invs[N * N];
__device__ float  g_invt[N * N];
__device__ double g_sum;

// ---------------------------------------------------------------------------
__global__ void rkd_zero_kernel() { g_sum = 0.0; }

// ---------------------------------------------------------------------------
// Gram: G = E * E^T, E is [N, D].  grid (24, 24, 2), block (16, 16).
__global__ void rkd_gram_kernel(const float* __restrict__ S,
                                const float* __restrict__ T) {
    const float* __restrict__ E = (blockIdx.z == 0) ? S : T;
    float* __restrict__ G = (blockIdx.z == 0) ? g_Gs : g_Gt;

    __shared__ float As[16][17];
    __shared__ float Bs[16][17];

    int tx = threadIdx.x, ty = threadIdx.y;
    int j = blockIdx.y * 16 + ty;
    int k = blockIdx.x * 16 + tx;

    float acc = 0.f;
    for (int kc = 0; kc < D; kc += 16) {
        As[ty][tx] = E[(blockIdx.y * 16 + ty) * D + kc + tx];
        Bs[ty][tx] = E[(blockIdx.x * 16 + ty) * D + kc + tx];
        __syncthreads();
#pragma unroll
        for (int p = 0; p < 16; p++)
            acc = fmaf(As[ty][p], Bs[tx][p], acc);
        __syncthreads();
    }
    G[j * N + k] = acc;
}

// ---------------------------------------------------------------------------
// inv[i][j] = 1 / max(||e_j - e_i||, eps), with inv[i][i] forced to 0 so the
// degenerate (zero-diff) triplets contribute exactly 0 like the reference.
// grid 576 blocks x 256 threads = N*N
__global__ void rkd_inv_kernel() {
    int idx = blockIdx.x * 256 + threadIdx.x;
    int i = idx / N;
    int j = idx - i * N;

    float gs_jj = g_Gs[j * N + j];
    float gs_ij = g_Gs[i * N + j];
    float gs_ii = g_Gs[i * N + i];
    float n2s = fmaxf(gs_jj - 2.f * gs_ij + gs_ii, 0.f);
    float invs = (i == j) ? 0.f : (1.f / fmaxf(sqrtf(n2s), EPSF));

    float gt_jj = g_Gt[j * N + j];
    float gt_ij = g_Gt[i * N + j];
    float gt_ii = g_Gt[i * N + i];
    float n2t = fmaxf(gt_jj - 2.f * gt_ij + gt_ii, 0.f);
    float invt = (i == j) ? 0.f : (1.f / fmaxf(sqrtf(n2t), EPSF));

    g_invs[idx] = invs;
    g_invt[idx] = invt;
}

// ---------------------------------------------------------------------------
// Main: for every anchor i and every (j,k):
//   num   = G[j,k] - G[i,k] - G[i,j] + G[i,i]
//   angle = num * inv[i,j] * inv[i,k]
//   loss += smoothL1(angle_s - angle_t)
// Block handles one 64x64 (j,k) tile of G (in smem) x TI anchors.
// 256 threads, 4x4 microtile per thread.
#define TI 24
__global__ void __launch_bounds__(256) rkd_angle_loss_kernel() {
    int tile = blockIdx.x;               // 0..35
    int tj = (tile / 6) * 64;
    int tk = (tile % 6) * 64;
    int i0 = blockIdx.y * TI;

    __shared__ float sGs[64][68];
    __shared__ float sGt[64][68];
    __shared__ float red[256];

    int tid = threadIdx.x;

    // cooperative tile load (coalesced float4)
    {
        int r0 = tid >> 4;
        int c4 = (tid & 15) << 2;
#pragma unroll
        for (int rr = 0; rr < 4; rr++) {
            int row = r0 + rr * 16;
            float4 vs = *reinterpret_cast<const float4*>(&g_Gs[(tj + row) * N + tk + c4]);
            float4 vt = *reinterpret_cast<const float4*>(&g_Gt[(tj + row) * N + tk + c4]);
            *reinterpret_cast<float4*>(&sGs[row][c4]) = vs;
            *reinterpret_cast<float4*>(&sGt[row][c4]) = vt;
        }
    }
    __syncthreads();

    int ty = tid >> 4;      // 0..15 -> j quad
    int tx = tid & 15;      // 0..15 -> k quad
    int jq = tj + ty * 4;   // this thread's 4 j indices: jq..jq+3
    int kq = tk + tx * 4;   // this thread's 4 k indices: kq..kq+3

    float acc = 0.f;

    for (int i = i0; i < i0 + TI; i++) {
        const float gs_ii = g_Gs[i * N + i];
        const float gt_ii = g_Gt[i * N + i];

        float4 gj_s = *reinterpret_cast<const float4*>(&g_Gs[i * N + jq]);
        float4 gk_s = *reinterpret_cast<const float4*>(&g_Gs[i * N + kq]);
        float4 pj_s = *reinterpret_cast<const float4*>(&g_invs[i * N + jq]);
        float4 qk_s = *reinterpret_cast<const float4*>(&g_invs[i * N + kq]);

        float4 gj_t = *reinterpret_cast<const float4*>(&g_Gt[i * N + jq]);
        float4 gk_t = *reinterpret_cast<const float4*>(&g_Gt[i * N + kq]);
        float4 pj_t = *reinterpret_cast<const float4*>(&g_invt[i * N + jq]);
        float4 qk_t = *reinterpret_cast<const float4*>(&g_invt[i * N + kq]);

        // c_j = G_ii - G_ij ; r_k = G_ik ; pq = inv_ij * inv_ik
        float c_s[4] = {gs_ii - gj_s.x, gs_ii - gj_s.y, gs_ii - gj_s.z, gs_ii - gj_s.w};
        float c_t[4] = {gt_ii - gj_t.x, gt_ii - gj_t.y, gt_ii - gj_t.z, gt_ii - gj_t.w};
        float r_s[4] = {gk_s.x, gk_s.y, gk_s.z, gk_s.w};
        float r_t[4] = {gk_t.x, gk_t.y, gk_t.z, gk_t.w};
        float pj_sa[4] = {pj_s.x, pj_s.y, pj_s.z, pj_s.w};
        float qk_sa[4] = {qk_s.x, qk_s.y, qk_s.z, qk_s.w};
        float pj_ta[4] = {pj_t.x, pj_t.y, pj_t.z, pj_t.w};
        float qk_ta[4] = {qk_t.x, qk_t.y, qk_t.z, qk_t.w};

        float pq_s[4][4], pq_t[4][4];
#pragma unroll
        for (int jj = 0; jj < 4; jj++)
#pragma unroll
            for (int kk = 0; kk < 4; kk++) {
                pq_s[jj][kk] = pj_sa[jj] * qk_sa[kk];
                pq_t[jj][kk] = pj_ta[jj] * qk_ta[kk];
            }

#pragma unroll
        for (int jj = 0; jj < 4; jj++) {
            float4 gs4 = *reinterpret_cast<const float4*>(&sGs[ty * 4 + jj][tx * 4]);
            float4 gt4 = *reinterpret_cast<const float4*>(&sGt[ty * 4 + jj][tx * 4]);
            float gs[4] = {gs4.x, gs4.y, gs4.z, gs4.w};
            float gt[4] = {gt4.x, gt4.y, gt4.z, gt4.w};
#pragma unroll
            for (int kk = 0; kk < 4; kk++) {
                float as = ((gs[kk] - r_s[kk]) + c_s[jj]) * pq_s[jj][kk];
                float at = ((gt[kk] - r_t[kk]) + c_t[jj]) * pq_t[jj][kk];
                float x = fabsf(as - at);
                float l = (x < 1.f) ? (0.5f * x * x) : (x - 0.5f);
                acc += l;
            }
        }
    }

    // block reduction
    red[tid] = acc;
    __syncthreads();
#pragma unroll
    for (int s = 128; s > 0; s >>= 1) {
        if (tid < s) red[tid] += red[tid + s];
        __syncthreads();
    }
    if (tid == 0) atomicAdd(&g_sum, (double)red[0]);
}

// ---------------------------------------------------------------------------
__global__ void rkd_finalize_kernel(float* __restrict__ out) {
    double n3 = (double)N * (double)N * (double)N;
    out[0] = (float)(g_sum / n3);
}

// ---------------------------------------------------------------------------
extern "C" void kernel_launch(void* const* d_in, const int* in_sizes, int n_in,
                              void* d_out, int out_size) {
    const float* student = (const float*)d_in[0];
    const float* teacher = (const float*)d_in[1];
    float* out = (float*)d_out;

    rkd_zero_kernel<<<1, 1>>>();

    dim3 gblk(16, 16);
    dim3 ggrd(N / 16, N / 16, 2);
    rkd_gram_kernel<<<ggrd, gblk>>>(student, teacher);

    rkd_inv_kernel<<<(N * N) / 256, 256>>>();

    dim3 mgrd(36, N / TI);
    rkd_angle_loss_kernel<<<mgrd, 256>>>();

    rkd_finalize_kernel<<<1, 1>>>(out);
}

// round 2
// speedup vs baseline: 1.8536x; 1.8536x over previous
#include <cuda_runtime.h>

#define N 384
#define D 256
#define EPSF 1e-12f

typedef unsigned long long u64;

// scratch (no allocation allowed)
__device__ float  g_Gs[N * N];
__device__ float  g_Gt[N * N];
__device__ float  g_invs[N * N];
__device__ float  g_invt[N * N];
__device__ float  g_cs[N * N];
__device__ float  g_ct[N * N];
__device__ double g_sum;

// upper-triangle 64x64 tile enumeration (a <= b), 21 tiles over a 6x6 grid
__constant__ int c_TA[21] = {0,0,0,0,0,0,1,1,1,1,1,2,2,2,2,3,3,3,4,4,5};
__constant__ int c_TB[21] = {0,1,2,3,4,5,1,2,3,4,5,2,3,4,5,3,4,5,4,5,5};

// ---------------------------------------------------------------------------
// packed f32x2 helpers (sm_103a)
__device__ __forceinline__ u64 pack2(float lo, float hi) {
    u64 r; asm("mov.b64 %0,{%1,%2};" : "=l"(r) : "f"(lo), "f"(hi)); return r;
}
__device__ __forceinline__ float2 unpack2(u64 v) {
    float2 f; asm("mov.b64 {%0,%1},%2;" : "=f"(f.x), "=f"(f.y) : "l"(v)); return f;
}
__device__ __forceinline__ u64 add2(u64 a, u64 b) {
    u64 r; asm("add.rn.f32x2 %0,%1,%2;" : "=l"(r) : "l"(a), "l"(b)); return r;
}
__device__ __forceinline__ u64 mul2(u64 a, u64 b) {
    u64 r; asm("mul.rn.f32x2 %0,%1,%2;" : "=l"(r) : "l"(a), "l"(b)); return r;
}
__device__ __forceinline__ u64 fma2(u64 a, u64 b, u64 c) {
    u64 r; asm("fma.rn.f32x2 %0,%1,%2,%3;" : "=l"(r) : "l"(a), "l"(b), "l"(c)); return r;
}

// ---------------------------------------------------------------------------
// Gram: G = E * E^T.  grid (12, 12, 2), 256 threads, 32x32 tile, 2x2 micro.
__global__ void __launch_bounds__(256) rkd_gram_kernel(const float* __restrict__ S,
                                                       const float* __restrict__ T) {
    const float* __restrict__ E = (blockIdx.z == 0) ? S : T;
    float* __restrict__ G = (blockIdx.z == 0) ? g_Gs : g_Gt;

    __shared__ float As[32][34];   // [k][row], padded
    __shared__ float Bs[32][34];

    int tid = threadIdx.x;
    int ty = tid >> 4, tx = tid & 15;
    int row = tid >> 3;          // 0..31
    int c4 = (tid & 7) * 4;      // 0..28

    int tj = blockIdx.y * 32, tk = blockIdx.x * 32;

    float a00 = 0.f, a01 = 0.f, a10 = 0.f, a11 = 0.f;

    for (int kc = 0; kc < D; kc += 32) {
        float4 av = *reinterpret_cast<const float4*>(&E[(tj + row) * D + kc + c4]);
        float4 bv = *reinterpret_cast<const float4*>(&E[(tk + row) * D + kc + c4]);
        As[c4 + 0][row] = av.x; As[c4 + 1][row] = av.y;
        As[c4 + 2][row] = av.z; As[c4 + 3][row] = av.w;
        Bs[c4 + 0][row] = bv.x; Bs[c4 + 1][row] = bv.y;
        Bs[c4 + 2][row] = bv.z; Bs[c4 + 3][row] = bv.w;
        __syncthreads();
#pragma unroll
        for (int kk = 0; kk < 32; kk++) {
            float2 a2 = *reinterpret_cast<const float2*>(&As[kk][ty * 2]);
            float2 b2 = *reinterpret_cast<const float2*>(&Bs[kk][tx * 2]);
            a00 = fmaf(a2.x, b2.x, a00);
            a01 = fmaf(a2.x, b2.y, a01);
            a10 = fmaf(a2.y, b2.x, a10);
            a11 = fmaf(a2.y, b2.y, a11);
        }
        __syncthreads();
    }
    int j = tj + ty * 2, k = tk + tx * 2;
    G[j * N + k]           = a00;
    G[j * N + k + 1]       = a01;
    G[(j + 1) * N + k]     = a10;
    G[(j + 1) * N + k + 1] = a11;
}

// ---------------------------------------------------------------------------
// inv[i][j] = 1/max(||e_j - e_i||, eps), inv[i][i] = 0; also c[i][j] = G_ii - G_ij.
// Also zeroes g_sum (runs before the loss kernel). grid 576 x 256.
__global__ void rkd_inv_kernel() {
    int idx = blockIdx.x * 256 + threadIdx.x;
    int i = idx / N;
    int j = idx - i * N;
    if (idx == 0) g_sum = 0.0;

    float gs_ii = g_Gs[i * N + i];
    float gs_jj = g_Gs[j * N + j];
    float gs_ij = g_Gs[idx];
    float cs = gs_ii - gs_ij;
    float n2s = fmaxf((gs_jj - gs_ij) + cs, 0.f);
    float invs = (i == j) ? 0.f : (1.f / fmaxf(sqrtf(n2s), EPSF));

    float gt_ii = g_Gt[i * N + i];
    float gt_jj = g_Gt[j * N + j];
    float gt_ij = g_Gt[idx];
    float ct = gt_ii - gt_ij;
    float n2t = fmaxf((gt_jj - gt_ij) + ct, 0.f);
    float invt = (i == j) ? 0.f : (1.f / fmaxf(sqrtf(n2t), EPSF));

    g_invs[idx] = invs;
    g_cs[idx] = cs;
    g_invt[idx] = invt;
    g_ct[idx] = ct;
}

// ---------------------------------------------------------------------------
// Main: only upper-triangle (j,k) tiles; off-diagonal tiles weighted x2.
//   angle = (G[j,k] + c[i,j] - G[i,k]) * inv[i,j] * inv[i,k]
//   loss += smoothL1(angle_s - angle_t)   via y=min(|d|,1); y*(|d|-0.5y)
// G microtile lives in registers; all elementwise math is packed f32x2.
#define TI 16
__global__ void __launch_bounds__(256, 2) rkd_angle_loss_kernel() {
    int a = c_TA[blockIdx.x], b = c_TB[blockIdx.x];
    int tj = a * 64, tk = b * 64;
    int i0 = blockIdx.y * TI;

    int tid = threadIdx.x;
    int ty = tid >> 4, tx = tid & 15;
    int jq = tj + ty * 4, kq = tk + tx * 4;

    // G microtile (4x4, both sides) in registers as packed pairs
    u64 G2s[4][2], G2t[4][2];
#pragma unroll
    for (int jj = 0; jj < 4; jj++) {
        float4 vs = *reinterpret_cast<const float4*>(&g_Gs[(jq + jj) * N + kq]);
        float4 vt = *reinterpret_cast<const float4*>(&g_Gt[(jq + jj) * N + kq]);
        G2s[jj][0] = pack2(vs.x, vs.y); G2s[jj][1] = pack2(vs.z, vs.w);
        G2t[jj][0] = pack2(vt.x, vt.y); G2t[jj][1] = pack2(vt.z, vt.w);
    }

    const u64 NEG1 = 0xBF800000BF800000ULL;  // {-1.f, -1.f}
    const u64 MH   = 0xBF000000BF000000ULL;  // {-0.5f, -0.5f}

    u64 acc2 = 0ULL;

    for (int i = i0; i < i0 + TI; i++) {
        int base = i * N;
        float4 cjs = *reinterpret_cast<const float4*>(&g_cs[base + jq]);
        float4 pjs = *reinterpret_cast<const float4*>(&g_invs[base + jq]);
        float4 rs  = *reinterpret_cast<const float4*>(&g_Gs[base + kq]);
        float4 qks = *reinterpret_cast<const float4*>(&g_invs[base + kq]);
        float4 cjt = *reinterpret_cast<const float4*>(&g_ct[base + jq]);
        float4 pjt = *reinterpret_cast<const float4*>(&g_invt[base + jq]);
        float4 rt  = *reinterpret_cast<const float4*>(&g_Gt[base + kq]);
        float4 qkt = *reinterpret_cast<const float4*>(&g_invt[base + kq]);

        u64 q2s[2] = { pack2(qks.x, qks.y), pack2(qks.z, qks.w) };
        u64 r2s[2] = { pack2(rs.x,  rs.y),  pack2(rs.z,  rs.w)  };
        u64 q2t[2] = { pack2(qkt.x, qkt.y), pack2(qkt.z, qkt.w) };
        u64 r2t[2] = { pack2(rt.x,  rt.y),  pack2(rt.z,  rt.w)  };

        float cjs_a[4] = {cjs.x, cjs.y, cjs.z, cjs.w};
        float pjs_a[4] = {pjs.x, pjs.y, pjs.z, pjs.w};
        float cjt_a[4] = {cjt.x, cjt.y, cjt.z, cjt.w};
        float pjt_a[4] = {pjt.x, pjt.y, pjt.z, pjt.w};

#pragma unroll
        for (int jj = 0; jj < 4; jj++) {
            u64 c2s = pack2(cjs_a[jj], cjs_a[jj]);
            u64 p2s = pack2(pjs_a[jj], pjs_a[jj]);
            u64 c2t = pack2(cjt_a[jj], cjt_a[jj]);
            u64 p2t = pack2(pjt_a[jj], pjt_a[jj]);
#pragma unroll
            for (int p = 0; p < 2; p++) {
                u64 ws  = fma2(r2s[p], NEG1, c2s);        // c - r
                u64 wt  = fma2(r2t[p], NEG1, c2t);
                u64 pqs = mul2(p2s, q2s[p]);
                u64 pqt = mul2(p2t, q2t[p]);
                u64 as2 = mul2(pqs, add2(G2s[jj][p], ws));
                u64 at2 = mul2(pqt, add2(G2t[jj][p], wt));
                u64 d2  = fma2(at2, NEG1, as2);           // as - at
                float2 d = unpack2(d2);
                float x0 = fabsf(d.x), x1 = fabsf(d.y);
                float y0 = fminf(x0, 1.f), y1 = fminf(x1, 1.f);
                u64 x2 = pack2(x0, x1);
                u64 y2 = pack2(y0, y1);
                u64 t2 = fma2(MH, y2, x2);                // x - 0.5y
                acc2 = fma2(y2, t2, acc2);                // += y*(x-0.5y)
            }
        }
    }

    float2 av = unpack2(acc2);
    float acc = av.x + av.y;

    __shared__ float red[256];
    red[tid] = acc;
    __syncthreads();
#pragma unroll
    for (int s = 128; s > 0; s >>= 1) {
        if (tid < s) red[tid] += red[tid + s];
        __syncthreads();
    }
    if (tid == 0) {
        double w = (a == b) ? 1.0 : 2.0;
        atomicAdd(&g_sum, (double)red[0] * w);
    }
}

// ---------------------------------------------------------------------------
__global__ void rkd_finalize_kernel(float* __restrict__ out) {
    double n3 = (double)N * (double)N * (double)N;
    out[0] = (float)(g_sum / n3);
}

// ---------------------------------------------------------------------------
extern "C" void kernel_launch(void* const* d_in, const int* in_sizes, int n_in,
                              void* d_out, int out_size) {
    const float* student = (const float*)d_in[0];
    const float* teacher = (const float*)d_in[1];
    float* out = (float*)d_out;

    dim3 ggrd(N / 32, N / 32, 2);
    rkd_gram_kernel<<<ggrd, 256>>>(student, teacher);

    rkd_inv_kernel<<<(N * N) / 256, 256>>>();

    dim3 mgrd(21, N / TI);
    rkd_angle_loss_kernel<<<mgrd, 256>>>();

    rkd_finalize_kernel<<<1, 1>>>(out);
}

// round 3
// speedup vs baseline: 1.8552x; 1.0009x over previous
#include <cuda_runtime.h>

#define N 384
#define D 256
#define EPSF 1e-12f
#define NTILES 21
#define NUNITS (NTILES * N)   // 8064
#define NBLK 296

typedef unsigned long long u64;

// scratch (no allocation allowed)
__device__ float  g_Gs[N * N];
__device__ float  g_Gt[N * N];
__device__ float  g_ps[N * N];     // inv_ij (student)
__device__ float  g_cps[N * N];    // (G_ii - G_ij) * inv_ij
__device__ float  g_nrqs[N * N];   // -G_ij * inv_ij
__device__ float  g_pt[N * N];
__device__ float  g_cpt[N * N];
__device__ float  g_nrqt[N * N];
__device__ double g_sum;
__device__ int    g_cnt;

// upper-triangle 64x64 tile enumeration (a <= b), 21 tiles over a 6x6 grid
__constant__ int c_TA[NTILES] = {0,0,0,0,0,0,1,1,1,1,1,2,2,2,2,3,3,3,4,4,5};
__constant__ int c_TB[NTILES] = {0,1,2,3,4,5,1,2,3,4,5,2,3,4,5,3,4,5,4,5,5};

// ---------------------------------------------------------------------------
// packed f32x2 helpers (sm_103a)
__device__ __forceinline__ u64 pack2(float lo, float hi) {
    u64 r; asm("mov.b64 %0,{%1,%2};" : "=l"(r) : "f"(lo), "f"(hi)); return r;
}
__device__ __forceinline__ float2 unpack2(u64 v) {
    float2 f; asm("mov.b64 {%0,%1},%2;" : "=f"(f.x), "=f"(f.y) : "l"(v)); return f;
}
__device__ __forceinline__ u64 mul2(u64 a, u64 b) {
    u64 r; asm("mul.rn.f32x2 %0,%1,%2;" : "=l"(r) : "l"(a), "l"(b)); return r;
}
__device__ __forceinline__ u64 fma2(u64 a, u64 b, u64 c) {
    u64 r; asm("fma.rn.f32x2 %0,%1,%2,%3;" : "=l"(r) : "l"(a), "l"(b), "l"(c)); return r;
}

// ---------------------------------------------------------------------------
// Gram: G = E * E^T.  grid (12, 12, 2), 256 threads, 32x32 tile, 2x2 micro.
__global__ void __launch_bounds__(256) rkd_gram_kernel(const float* __restrict__ S,
                                                       const float* __restrict__ T) {
    const float* __restrict__ E = (blockIdx.z == 0) ? S : T;
    float* __restrict__ G = (blockIdx.z == 0) ? g_Gs : g_Gt;

    __shared__ float As[32][34];   // [k][row], padded
    __shared__ float Bs[32][34];

    int tid = threadIdx.x;
    int ty = tid >> 4, tx = tid & 15;
    int row = tid >> 3;          // 0..31
    int c4 = (tid & 7) * 4;      // 0..28

    int tj = blockIdx.y * 32, tk = blockIdx.x * 32;

    float a00 = 0.f, a01 = 0.f, a10 = 0.f, a11 = 0.f;

    for (int kc = 0; kc < D; kc += 32) {
        float4 av = *reinterpret_cast<const float4*>(&E[(tj + row) * D + kc + c4]);
        float4 bv = *reinterpret_cast<const float4*>(&E[(tk + row) * D + kc + c4]);
        As[c4 + 0][row] = av.x; As[c4 + 1][row] = av.y;
        As[c4 + 2][row] = av.z; As[c4 + 3][row] = av.w;
        Bs[c4 + 0][row] = bv.x; Bs[c4 + 1][row] = bv.y;
        Bs[c4 + 2][row] = bv.z; Bs[c4 + 3][row] = bv.w;
        __syncthreads();
#pragma unroll
        for (int kk = 0; kk < 32; kk++) {
            float2 a2 = *reinterpret_cast<const float2*>(&As[kk][ty * 2]);
            float2 b2 = *reinterpret_cast<const float2*>(&Bs[kk][tx * 2]);
            a00 = fmaf(a2.x, b2.x, a00);
            a01 = fmaf(a2.x, b2.y, a01);
            a10 = fmaf(a2.y, b2.x, a10);
            a11 = fmaf(a2.y, b2.y, a11);
        }
        __syncthreads();
    }
    int j = tj + ty * 2, k = tk + tx * 2;
    G[j * N + k]           = a00;
    G[j * N + k + 1]       = a01;
    G[(j + 1) * N + k]     = a10;
    G[(j + 1) * N + k + 1] = a11;
}

// ---------------------------------------------------------------------------
// Precompute p = inv_ij (0 on diagonal), cp = (G_ii - G_ij)*p, nrq = -G_ij*p.
// Also zeroes g_sum / g_cnt. grid 576 x 256.
__global__ void rkd_inv_kernel() {
    int idx = blockIdx.x * 256 + threadIdx.x;
    int i = idx / N;
    int j = idx - i * N;
    if (idx == 0) { g_sum = 0.0; g_cnt = 0; }

    float gs_ii = g_Gs[i * N + i];
    float gs_jj = g_Gs[j * N + j];
    float gs_ij = g_Gs[idx];
    float cs = gs_ii - gs_ij;
    float n2s = fmaxf((gs_jj - gs_ij) + cs, 0.f);
    float ps = (i == j) ? 0.f : (1.f / fmaxf(sqrtf(n2s), EPSF));

    float gt_ii = g_Gt[i * N + i];
    float gt_jj = g_Gt[j * N + j];
    float gt_ij = g_Gt[idx];
    float ct = gt_ii - gt_ij;
    float n2t = fmaxf((gt_jj - gt_ij) + ct, 0.f);
    float pt = (i == j) ? 0.f : (1.f / fmaxf(sqrtf(n2t), EPSF));

    g_ps[idx]   = ps;
    g_cps[idx]  = cs * ps;
    g_nrqs[idx] = -gs_ij * ps;
    g_pt[idx]   = pt;
    g_cpt[idx]  = ct * pt;
    g_nrqt[idx] = -gt_ij * pt;
}

// ---------------------------------------------------------------------------
// Main: balanced flatten of 8064 (tile, i) units over exactly NBLK blocks.
//   angle = q_k*(p_j*G_jk + cp_j) + nrq_k*p_j
//   loss += smoothL1(angle_s - angle_t); off-diagonal tiles weighted x2.
// Last block finalizes the scalar output.
__global__ void __launch_bounds__(256, 2) rkd_angle_loss_kernel(float* __restrict__ out) {
    int tid = threadIdx.x;
    int ty = tid >> 4, tx = tid & 15;
    int b = blockIdx.x;

    int u0 = (b * NUNITS) / NBLK;
    int u1 = ((b + 1) * NUNITS) / NBLK;
    int tile = u0 / N;
    int i = u0 - tile * N;
    int remaining = u1 - u0;

    const u64 NEG1 = 0xBF800000BF800000ULL;  // {-1.f, -1.f}

    float wacc = 0.f;

    while (remaining > 0) {
        int cnt = min(N - i, remaining);
        remaining -= cnt;

        int jq = c_TA[tile] * 64 + ty * 4;
        int kq = c_TB[tile] * 64 + tx * 4;

        // G microtile (4x4, both sides) in registers as packed pairs
        u64 G2s[4][2], G2t[4][2];
#pragma unroll
        for (int jj = 0; jj < 4; jj++) {
            float4 vs = *reinterpret_cast<const float4*>(&g_Gs[(jq + jj) * N + kq]);
            float4 vt = *reinterpret_cast<const float4*>(&g_Gt[(jq + jj) * N + kq]);
            G2s[jj][0] = pack2(vs.x, vs.y); G2s[jj][1] = pack2(vs.z, vs.w);
            G2t[jj][0] = pack2(vt.x, vt.y); G2t[jj][1] = pack2(vt.z, vt.w);
        }

        float acc0 = 0.f, acc1 = 0.f;

        for (int s = 0; s < cnt; s++, i++) {
            int base = i * N;
            float4 pj_s = *reinterpret_cast<const float4*>(&g_ps[base + jq]);
            float4 cj_s = *reinterpret_cast<const float4*>(&g_cps[base + jq]);
            float4 qk_s = *reinterpret_cast<const float4*>(&g_ps[base + kq]);
            float4 nr_s = *reinterpret_cast<const float4*>(&g_nrqs[base + kq]);
            float4 pj_t = *reinterpret_cast<const float4*>(&g_pt[base + jq]);
            float4 cj_t = *reinterpret_cast<const float4*>(&g_cpt[base + jq]);
            float4 qk_t = *reinterpret_cast<const float4*>(&g_pt[base + kq]);
            float4 nr_t = *reinterpret_cast<const float4*>(&g_nrqt[base + kq]);

            u64 q2s[2] = { pack2(qk_s.x, qk_s.y), pack2(qk_s.z, qk_s.w) };
            u64 n2s[2] = { pack2(nr_s.x, nr_s.y), pack2(nr_s.z, nr_s.w) };
            u64 q2t[2] = { pack2(qk_t.x, qk_t.y), pack2(qk_t.z, qk_t.w) };
            u64 n2t[2] = { pack2(nr_t.x, nr_t.y), pack2(nr_t.z, nr_t.w) };

            float pjs_a[4] = {pj_s.x, pj_s.y, pj_s.z, pj_s.w};
            float cjs_a[4] = {cj_s.x, cj_s.y, cj_s.z, cj_s.w};
            float pjt_a[4] = {pj_t.x, pj_t.y, pj_t.z, pj_t.w};
            float cjt_a[4] = {cj_t.x, cj_t.y, cj_t.z, cj_t.w};

#pragma unroll
            for (int jj = 0; jj < 4; jj++) {
                u64 p2s = pack2(pjs_a[jj], pjs_a[jj]);
                u64 c2s = pack2(cjs_a[jj], cjs_a[jj]);
                u64 p2t = pack2(pjt_a[jj], pjt_a[jj]);
                u64 c2t = pack2(cjt_a[jj], cjt_a[jj]);
#pragma unroll
                for (int p = 0; p < 2; p++) {
                    u64 t2s = fma2(p2s, G2s[jj][p], c2s);
                    u64 m2s = mul2(n2s[p], p2s);
                    u64 a2s = fma2(q2s[p], t2s, m2s);
                    u64 t2t = fma2(p2t, G2t[jj][p], c2t);
                    u64 m2t = mul2(n2t[p], p2t);
                    u64 a2t = fma2(q2t[p], t2t, m2t);
                    u64 d2  = fma2(a2t, NEG1, a2s);      // as - at
                    float2 d = unpack2(d2);
                    float x0 = fabsf(d.x), x1 = fabsf(d.y);
                    float y0 = fminf(x0, 1.f), y1 = fminf(x1, 1.f);
                    float t0 = fmaf(y0, -0.5f, x0);
                    float t1 = fmaf(y1, -0.5f, x1);
                    acc0 = fmaf(y0, t0, acc0);
                    acc1 = fmaf(y1, t1, acc1);
                }
            }
        }

        float w = (c_TA[tile] == c_TB[tile]) ? 1.f : 2.f;
        wacc = fmaf(w, acc0 + acc1, wacc);
        tile++;
        i = 0;
    }

    // block reduction
    __shared__ float red[256];
    red[tid] = wacc;
    __syncthreads();
#pragma unroll
    for (int s = 128; s > 0; s >>= 1) {
        if (tid < s) red[tid] += red[tid + s];
        __syncthreads();
    }
    if (tid == 0) {
        atomicAdd(&g_sum, (double)red[0]);
        __threadfence();
        int t = atomicAdd(&g_cnt, 1);
        if (t == NBLK - 1) {
            double n3 = (double)N * (double)N * (double)N;
            out[0] = (float)(g_sum / n3);
        }
    }
}

// ---------------------------------------------------------------------------
extern "C" void kernel_launch(void* const* d_in, const int* in_sizes, int n_in,
                              void* d_out, int out_size) {
    const float* student = (const float*)d_in[0];
    const float* teacher = (const float*)d_in[1];
    float* out = (float*)d_out;

    dim3 ggrd(N / 32, N / 32, 2);
    rkd_gram_kernel<<<ggrd, 256>>>(student, teacher);

    rkd_inv_kernel<<<(N * N) / 256, 256>>>();

    rkd_angle_loss_kernel<<<NBLK, 256>>>(out);
}

// round 4
// speedup vs baseline: 1.9746x; 1.0644x over previous
#include <cuda_runtime.h>

#define N 384
#define D 256
#define EPSF 1e-12f
#define NTILES 21
#define NUNITS (NTILES * N)   // 8064
#define NBLK 296

typedef unsigned long long u64;

// scratch (no allocation allowed)
__device__ float  g_Gs[N * N];
__device__ float  g_Gt[N * N];
__device__ float  g_diag[2][N];
__device__ float  g_ps[N * N];     // inv_ij (student)
__device__ float  g_cps[N * N];    // (G_ii - G_ij) * inv_ij
__device__ float  g_nrqs[N * N];   // -G_ij * inv_ij
__device__ float  g_pt[N * N];
__device__ float  g_cpt[N * N];
__device__ float  g_nrqt[N * N];
__device__ double g_sum;

// upper-triangle 64x64 tile enumeration (a <= b), 21 tiles over a 6x6 grid
__constant__ int c_TA[NTILES] = {0,0,0,0,0,0,1,1,1,1,1,2,2,2,2,3,3,3,4,4,5};
__constant__ int c_TB[NTILES] = {0,1,2,3,4,5,1,2,3,4,5,2,3,4,5,3,4,5,4,5,5};

// ---------------------------------------------------------------------------
// packed f32x2 helpers (sm_103a)
__device__ __forceinline__ u64 pack2(float lo, float hi) {
    u64 r; asm("mov.b64 %0,{%1,%2};" : "=l"(r) : "f"(lo), "f"(hi)); return r;
}
__device__ __forceinline__ float2 unpack2(u64 v) {
    float2 f; asm("mov.b64 {%0,%1},%2;" : "=f"(f.x), "=f"(f.y) : "l"(v)); return f;
}
__device__ __forceinline__ u64 mul2(u64 a, u64 b) {
    u64 r; asm("mul.rn.f32x2 %0,%1,%2;" : "=l"(r) : "l"(a), "l"(b)); return r;
}
__device__ __forceinline__ u64 fma2(u64 a, u64 b, u64 c) {
    u64 r; asm("fma.rn.f32x2 %0,%1,%2,%3;" : "=l"(r) : "l"(a), "l"(b), "l"(c)); return r;
}

// ---------------------------------------------------------------------------
// Gram: G = E * E^T.  grid (6, 12, 2): 64-wide k tile, 32-tall j tile.
// 256 threads, 2x4 microtile -> 8 FMA per LDS.64+LDS.128 pair.
// Blocks containing diagonal elements also write g_diag.
__global__ void __launch_bounds__(256) rkd_gram_kernel(const float* __restrict__ S,
                                                       const float* __restrict__ T) {
    const float* __restrict__ E = (blockIdx.z == 0) ? S : T;
    float* __restrict__ G = (blockIdx.z == 0) ? g_Gs : g_Gt;

    __shared__ float As[32][34];   // [kc][j]
    __shared__ float Bs[32][68];   // [kc][k], 16B-aligned rows

    int tid = threadIdx.x;
    int ty = tid >> 4, tx = tid & 15;      // ty: j-pair 0..15, tx: k-quad 0..15
    int row = tid >> 3;                    // 0..31
    int c4 = (tid & 7) * 4;                // 0..28

    int tj = blockIdx.y * 32, tk = blockIdx.x * 64;

    float acc[2][4];
#pragma unroll
    for (int r = 0; r < 2; r++)
#pragma unroll
        for (int c = 0; c < 4; c++) acc[r][c] = 0.f;

    for (int kc = 0; kc < D; kc += 32) {
        float4 av  = *reinterpret_cast<const float4*>(&E[(tj + row) * D + kc + c4]);
        float4 bv0 = *reinterpret_cast<const float4*>(&E[(tk + row) * D + kc + c4]);
        float4 bv1 = *reinterpret_cast<const float4*>(&E[(tk + 32 + row) * D + kc + c4]);
        As[c4 + 0][row] = av.x;  As[c4 + 1][row] = av.y;
        As[c4 + 2][row] = av.z;  As[c4 + 3][row] = av.w;
        Bs[c4 + 0][row] = bv0.x; Bs[c4 + 1][row] = bv0.y;
        Bs[c4 + 2][row] = bv0.z; Bs[c4 + 3][row] = bv0.w;
        Bs[c4 + 0][row + 32] = bv1.x; Bs[c4 + 1][row + 32] = bv1.y;
        Bs[c4 + 2][row + 32] = bv1.z; Bs[c4 + 3][row + 32] = bv1.w;
        __syncthreads();
#pragma unroll
        for (int kk = 0; kk < 32; kk++) {
            float2 a2 = *reinterpret_cast<const float2*>(&As[kk][ty * 2]);
            float4 b4 = *reinterpret_cast<const float4*>(&Bs[kk][tx * 4]);
            acc[0][0] = fmaf(a2.x, b4.x, acc[0][0]);
            acc[0][1] = fmaf(a2.x, b4.y, acc[0][1]);
            acc[0][2] = fmaf(a2.x, b4.z, acc[0][2]);
            acc[0][3] = fmaf(a2.x, b4.w, acc[0][3]);
            acc[1][0] = fmaf(a2.y, b4.x, acc[1][0]);
            acc[1][1] = fmaf(a2.y, b4.y, acc[1][1]);
            acc[1][2] = fmaf(a2.y, b4.z, acc[1][2]);
            acc[1][3] = fmaf(a2.y, b4.w, acc[1][3]);
        }
        __syncthreads();
    }

    int jg = tj + ty * 2;
    int kg = tk + tx * 4;
#pragma unroll
    for (int r = 0; r < 2; r++) {
        *reinterpret_cast<float4*>(&G[(jg + r) * N + kg]) =
            make_float4(acc[r][0], acc[r][1], acc[r][2], acc[r][3]);
        int d = (jg + r) - kg;
        if (d >= 0 && d < 4) {
            float v = (d == 0) ? acc[r][0] : (d == 1) ? acc[r][1]
                    : (d == 2) ? acc[r][2] : acc[r][3];
            g_diag[blockIdx.z][jg + r] = v;
        }
    }
}

// ---------------------------------------------------------------------------
// Precompute p = inv_ij (0 on diagonal), cp = (G_ii - G_ij)*p, nrq = -G_ij*p.
// Vectorized x4 (384 % 4 == 0 so a thread never crosses a row).
// Also zeroes g_sum. grid 144 x 256.
__global__ void __launch_bounds__(256) rkd_inv_kernel() {
    int g = blockIdx.x * 256 + threadIdx.x;
    int idx = g * 4;
    int i = idx / N;
    int j0 = idx - i * N;
    if (g == 0) g_sum = 0.0;

    float4 gs = *reinterpret_cast<const float4*>(&g_Gs[idx]);
    float4 gt = *reinterpret_cast<const float4*>(&g_Gt[idx]);
    float4 djs = *reinterpret_cast<const float4*>(&g_diag[0][j0]);
    float4 djt = *reinterpret_cast<const float4*>(&g_diag[1][j0]);
    float dis = g_diag[0][i];
    float dit = g_diag[1][i];

    float gs_a[4] = {gs.x, gs.y, gs.z, gs.w};
    float gt_a[4] = {gt.x, gt.y, gt.z, gt.w};
    float djs_a[4] = {djs.x, djs.y, djs.z, djs.w};
    float djt_a[4] = {djt.x, djt.y, djt.z, djt.w};

    float4 ps4, cps4, nrs4, pt4, cpt4, nrt4;
    float* ps_o = &ps4.x; float* cps_o = &cps4.x; float* nrs_o = &nrs4.x;
    float* pt_o = &pt4.x; float* cpt_o = &cpt4.x; float* nrt_o = &nrt4.x;

#pragma unroll
    for (int u = 0; u < 4; u++) {
        int j = j0 + u;
        float cs = dis - gs_a[u];
        float n2s = fmaxf((djs_a[u] - gs_a[u]) + cs, 0.f);
        float ps = (i == j) ? 0.f : (1.f / fmaxf(sqrtf(n2s), EPSF));
        ps_o[u] = ps;
        cps_o[u] = cs * ps;
        nrs_o[u] = -gs_a[u] * ps;

        float ct = dit - gt_a[u];
        float n2t = fmaxf((djt_a[u] - gt_a[u]) + ct, 0.f);
        float pt = (i == j) ? 0.f : (1.f / fmaxf(sqrtf(n2t), EPSF));
        pt_o[u] = pt;
        cpt_o[u] = ct * pt;
        nrt_o[u] = -gt_a[u] * pt;
    }

    *reinterpret_cast<float4*>(&g_ps[idx])   = ps4;
    *reinterpret_cast<float4*>(&g_cps[idx])  = cps4;
    *reinterpret_cast<float4*>(&g_nrqs[idx]) = nrs4;
    *reinterpret_cast<float4*>(&g_pt[idx])   = pt4;
    *reinterpret_cast<float4*>(&g_cpt[idx])  = cpt4;
    *reinterpret_cast<float4*>(&g_nrqt[idx]) = nrt4;
}

// ---------------------------------------------------------------------------
// Main: balanced flatten of 8064 (tile, i) units over exactly NBLK blocks.
//   angle = q_k*(p_j*G_jk + cp_j) + nrq_k*p_j
//   loss += smoothL1(angle_s - angle_t); off-diagonal tiles weighted x2.
__global__ void __launch_bounds__(256, 2) rkd_angle_loss_kernel(float* __restrict__ out) {
    int tid = threadIdx.x;
    int ty = tid >> 4, tx = tid & 15;
    int b = blockIdx.x;

    int u0 = (b * NUNITS) / NBLK;
    int u1 = ((b + 1) * NUNITS) / NBLK;
    int tile = u0 / N;
    int i = u0 - tile * N;
    int remaining = u1 - u0;

    const u64 NEG1 = 0xBF800000BF800000ULL;  // {-1.f, -1.f}

    float wacc = 0.f;

    while (remaining > 0) {
        int cnt = min(N - i, remaining);
        remaining -= cnt;

        int jq = c_TA[tile] * 64 + ty * 4;
        int kq = c_TB[tile] * 64 + tx * 4;

        // G microtile (4x4, both sides) in registers as packed pairs
        u64 G2s[4][2], G2t[4][2];
#pragma unroll
        for (int jj = 0; jj < 4; jj++) {
            float4 vs = *reinterpret_cast<const float4*>(&g_Gs[(jq + jj) * N + kq]);
            float4 vt = *reinterpret_cast<const float4*>(&g_Gt[(jq + jj) * N + kq]);
            G2s[jj][0] = pack2(vs.x, vs.y); G2s[jj][1] = pack2(vs.z, vs.w);
            G2t[jj][0] = pack2(vt.x, vt.y); G2t[jj][1] = pack2(vt.z, vt.w);
        }

        float acc0 = 0.f, acc1 = 0.f;

#pragma unroll 2
        for (int s = 0; s < cnt; s++) {
            int base = (i + s) * N;
            float4 pj_s = *reinterpret_cast<const float4*>(&g_ps[base + jq]);
            float4 cj_s = *reinterpret_cast<const float4*>(&g_cps[base + jq]);
            float4 qk_s = *reinterpret_cast<const float4*>(&g_ps[base + kq]);
            float4 nr_s = *reinterpret_cast<const float4*>(&g_nrqs[base + kq]);
            float4 pj_t = *reinterpret_cast<const float4*>(&g_pt[base + jq]);
            float4 cj_t = *reinterpret_cast<const float4*>(&g_cpt[base + jq]);
            float4 qk_t = *reinterpret_cast<const float4*>(&g_pt[base + kq]);
            float4 nr_t = *reinterpret_cast<const float4*>(&g_nrqt[base + kq]);

            u64 q2s[2] = { pack2(qk_s.x, qk_s.y), pack2(qk_s.z, qk_s.w) };
            u64 n2s[2] = { pack2(nr_s.x, nr_s.y), pack2(nr_s.z, nr_s.w) };
            u64 q2t[2] = { pack2(qk_t.x, qk_t.y), pack2(qk_t.z, qk_t.w) };
            u64 n2t[2] = { pack2(nr_t.x, nr_t.y), pack2(nr_t.z, nr_t.w) };

            float pjs_a[4] = {pj_s.x, pj_s.y, pj_s.z, pj_s.w};
            float cjs_a[4] = {cj_s.x, cj_s.y, cj_s.z, cj_s.w};
            float pjt_a[4] = {pj_t.x, pj_t.y, pj_t.z, pj_t.w};
            float cjt_a[4] = {cj_t.x, cj_t.y, cj_t.z, cj_t.w};

#pragma unroll
            for (int jj = 0; jj < 4; jj++) {
                u64 p2s = pack2(pjs_a[jj], pjs_a[jj]);
                u64 c2s = pack2(cjs_a[jj], cjs_a[jj]);
                u64 p2t = pack2(pjt_a[jj], pjt_a[jj]);
                u64 c2t = pack2(cjt_a[jj], cjt_a[jj]);
#pragma unroll
                for (int p = 0; p < 2; p++) {
                    u64 t2s = fma2(p2s, G2s[jj][p], c2s);
                    u64 m2s = mul2(n2s[p], p2s);
                    u64 a2s = fma2(q2s[p], t2s, m2s);
                    u64 t2t = fma2(p2t, G2t[jj][p], c2t);
                    u64 m2t = mul2(n2t[p], p2t);
                    u64 a2t = fma2(q2t[p], t2t, m2t);
                    u64 d2  = fma2(a2t, NEG1, a2s);      // as - at
                    float2 d = unpack2(d2);
                    float x0 = fabsf(d.x), x1 = fabsf(d.y);
                    float y0 = fminf(x0, 1.f), y1 = fminf(x1, 1.f);
                    float t0 = fmaf(y0, -0.5f, x0);
                    float t1 = fmaf(y1, -0.5f, x1);
                    acc0 = fmaf(y0, t0, acc0);
                    acc1 = fmaf(y1, t1, acc1);
                }
            }
        }

        float w = (c_TA[tile] == c_TB[tile]) ? 1.f : 2.f;
        wacc = fmaf(w, acc0 + acc1, wacc);
        tile++;
        i = 0;
    }

    // block reduction
    __shared__ float red[256];
    red[tid] = wacc;
    __syncthreads();
#pragma unroll
    for (int s = 128; s > 0; s >>= 1) {
        if (tid < s) red[tid] += red[tid + s];
        __syncthreads();
    }
    if (tid == 0) atomicAdd(&g_sum, (double)red[0]);
}

// ---------------------------------------------------------------------------
__global__ void rkd_finalize_kernel(float* __restrict__ out) {
    double n3 = (double)N * (double)N * (double)N;
    out[0] = (float)(g_sum / n3);
}

// ---------------------------------------------------------------------------
extern "C" void kernel_launch(void* const* d_in, const int* in_sizes, int n_in,
                              void* d_out, int out_size) {
    const float* student = (const float*)d_in[0];
    const float* teacher = (const float*)d_in[1];
    float* out = (float*)d_out;

    dim3 ggrd(N / 64, N / 32, 2);
    rkd_gram_kernel<<<ggrd, 256>>>(student, teacher);

    rkd_inv_kernel<<<(N * N) / 4 / 256, 256>>>();

    rkd_angle_loss_kernel<<<NBLK, 256>>>(out);

    rkd_finalize_kernel<<<1, 1>>>(out);
}

// round 5
// speedup vs baseline: 2.0942x; 1.0606x over previous
#include <cuda_runtime.h>

#define N 384
#define D 256
#define EPSF 1e-12f
#define NTILES 21
#define NUNITS (NTILES * N)   // 8064
#define NBLK 296

typedef unsigned long long u64;

// scratch (no allocation allowed)
__device__ float  g_Gs[N * N];
__device__ float  g_Gt[N * N];
__device__ float  g_ps[N * N];     // inv_ij (student)
__device__ float  g_cps[N * N];    // (G_ii - G_ij) * inv_ij
__device__ float  g_nrqs[N * N];   // -G_ij * inv_ij
__device__ float  g_pt[N * N];
__device__ float  g_cpt[N * N];
__device__ float  g_nrqt[N * N];
__device__ double g_sum;
__device__ int    g_cnt;

// upper-triangle 64x64 tile enumeration (a <= b), 21 tiles over a 6x6 grid
__constant__ int c_TA[NTILES] = {0,0,0,0,0,0,1,1,1,1,1,2,2,2,2,3,3,3,4,4,5};
__constant__ int c_TB[NTILES] = {0,1,2,3,4,5,1,2,3,4,5,2,3,4,5,3,4,5,4,5,5};

// ---------------------------------------------------------------------------
// packed f32x2 helpers (sm_103a)
__device__ __forceinline__ u64 pack2(float lo, float hi) {
    u64 r; asm("mov.b64 %0,{%1,%2};" : "=l"(r) : "f"(lo), "f"(hi)); return r;
}
__device__ __forceinline__ float2 unpack2(u64 v) {
    float2 f; asm("mov.b64 {%0,%1},%2;" : "=f"(f.x), "=f"(f.y) : "l"(v)); return f;
}
__device__ __forceinline__ u64 mul2(u64 a, u64 b) {
    u64 r; asm("mul.rn.f32x2 %0,%1,%2;" : "=l"(r) : "l"(a), "l"(b)); return r;
}
__device__ __forceinline__ u64 fma2(u64 a, u64 b, u64 c) {
    u64 r; asm("fma.rn.f32x2 %0,%1,%2,%3;" : "=l"(r) : "l"(a), "l"(b), "l"(c)); return r;
}

// ---------------------------------------------------------------------------
// Fused Gram + prep:  G = E*E^T on a 32(j) x 64(k) tile, plus diag via local
// sum-of-squares, plus the six prep arrays in the epilogue.
// grid (6, 12, 2), 256 threads, 2x4 microtile.
__global__ void __launch_bounds__(256) rkd_gram_prep_kernel(const float* __restrict__ S,
                                                            const float* __restrict__ T) {
    const float* __restrict__ E = (blockIdx.z == 0) ? S : T;
    float* __restrict__ G  = (blockIdx.z == 0) ? g_Gs   : g_Gt;
    float* __restrict__ P  = (blockIdx.z == 0) ? g_ps   : g_pt;
    float* __restrict__ CP = (blockIdx.z == 0) ? g_cps  : g_cpt;
    float* __restrict__ NR = (blockIdx.z == 0) ? g_nrqs : g_nrqt;

    __shared__ float As[32][34];   // [kc][j]
    __shared__ float Bs[32][68];   // [kc][k]
    __shared__ float dA[32];       // diag of j rows
    __shared__ float dB[64];       // diag of k rows

    int tid = threadIdx.x;
    if (blockIdx.x == 0 && blockIdx.y == 0 && blockIdx.z == 0 && tid == 0) {
        g_sum = 0.0; g_cnt = 0;
    }

    int ty = tid >> 4, tx = tid & 15;      // ty: j-pair 0..15, tx: k-quad 0..15
    int row = tid >> 3;                    // 0..31
    int c4 = (tid & 7) * 4;                // 0..28

    int tj = blockIdx.y * 32, tk = blockIdx.x * 64;

    float acc[2][4];
#pragma unroll
    for (int r = 0; r < 2; r++)
#pragma unroll
        for (int c = 0; c < 4; c++) acc[r][c] = 0.f;

    float ssA = 0.f, ssB0 = 0.f, ssB1 = 0.f;

    for (int kc = 0; kc < D; kc += 32) {
        float4 av  = *reinterpret_cast<const float4*>(&E[(tj + row) * D + kc + c4]);
        float4 bv0 = *reinterpret_cast<const float4*>(&E[(tk + row) * D + kc + c4]);
        float4 bv1 = *reinterpret_cast<const float4*>(&E[(tk + 32 + row) * D + kc + c4]);

        ssA  = fmaf(av.x,  av.x,  fmaf(av.y,  av.y,  fmaf(av.z,  av.z,  fmaf(av.w,  av.w,  ssA))));
        ssB0 = fmaf(bv0.x, bv0.x, fmaf(bv0.y, bv0.y, fmaf(bv0.z, bv0.z, fmaf(bv0.w, bv0.w, ssB0))));
        ssB1 = fmaf(bv1.x, bv1.x, fmaf(bv1.y, bv1.y, fmaf(bv1.z, bv1.z, fmaf(bv1.w, bv1.w, ssB1))));

        As[c4 + 0][row] = av.x;  As[c4 + 1][row] = av.y;
        As[c4 + 2][row] = av.z;  As[c4 + 3][row] = av.w;
        Bs[c4 + 0][row] = bv0.x; Bs[c4 + 1][row] = bv0.y;
        Bs[c4 + 2][row] = bv0.z; Bs[c4 + 3][row] = bv0.w;
        Bs[c4 + 0][row + 32] = bv1.x; Bs[c4 + 1][row + 32] = bv1.y;
        Bs[c4 + 2][row + 32] = bv1.z; Bs[c4 + 3][row + 32] = bv1.w;
        __syncthreads();
#pragma unroll
        for (int kk = 0; kk < 32; kk++) {
            float2 a2 = *reinterpret_cast<const float2*>(&As[kk][ty * 2]);
            float4 b4 = *reinterpret_cast<const float4*>(&Bs[kk][tx * 4]);
            acc[0][0] = fmaf(a2.x, b4.x, acc[0][0]);
            acc[0][1] = fmaf(a2.x, b4.y, acc[0][1]);
            acc[0][2] = fmaf(a2.x, b4.z, acc[0][2]);
            acc[0][3] = fmaf(a2.x, b4.w, acc[0][3]);
            acc[1][0] = fmaf(a2.y, b4.x, acc[1][0]);
            acc[1][1] = fmaf(a2.y, b4.y, acc[1][1]);
            acc[1][2] = fmaf(a2.y, b4.z, acc[1][2]);
            acc[1][3] = fmaf(a2.y, b4.w, acc[1][3]);
        }
        __syncthreads();
    }

    // reduce sum-of-squares over the 8 lanes sharing a row (contiguous lanes)
#pragma unroll
    for (int m = 4; m > 0; m >>= 1) {
        ssA  += __shfl_xor_sync(0xffffffffu, ssA,  m, 8);
        ssB0 += __shfl_xor_sync(0xffffffffu, ssB0, m, 8);
        ssB1 += __shfl_xor_sync(0xffffffffu, ssB1, m, 8);
    }
    if ((tid & 7) == 0) {
        dA[row] = ssA;
        dB[row] = ssB0;
        dB[row + 32] = ssB1;
    }
    __syncthreads();

    int jg = tj + ty * 2;
    int kg = tk + tx * 4;
#pragma unroll
    for (int r = 0; r < 2; r++) {
        int ig = jg + r;
        float di = dA[ty * 2 + r];

        float4 pv, cv, nv;
        float* pp = &pv.x; float* cp = &cv.x; float* np = &nv.x;
#pragma unroll
        for (int c = 0; c < 4; c++) {
            float gij = acc[r][c];
            float dj = dB[tx * 4 + c];
            float cs = di - gij;
            float n2 = fmaxf((dj - gij) + cs, 0.f);
            float p = (ig == kg + c) ? 0.f : (1.f / fmaxf(sqrtf(n2), EPSF));
            pp[c] = p;
            cp[c] = cs * p;
            np[c] = -gij * p;
        }
        *reinterpret_cast<float4*>(&G[ig * N + kg]) =
            make_float4(acc[r][0], acc[r][1], acc[r][2], acc[r][3]);
        *reinterpret_cast<float4*>(&P[ig * N + kg])  = pv;
        *reinterpret_cast<float4*>(&CP[ig * N + kg]) = cv;
        *reinterpret_cast<float4*>(&NR[ig * N + kg]) = nv;
    }
}

// ---------------------------------------------------------------------------
// Main: balanced flatten of 8064 (tile, i) units over exactly NBLK blocks.
//   angle = q_k*(p_j*G_jk + cp_j) + nrq_k*p_j
//   loss += smoothL1(angle_s - angle_t); off-diagonal tiles weighted x2.
// Last block to finish writes the final scalar.
__global__ void __launch_bounds__(256, 2) rkd_angle_loss_kernel(float* __restrict__ out) {
    int tid = threadIdx.x;
    int ty = tid >> 4, tx = tid & 15;
    int b = blockIdx.x;

    int u0 = (b * NUNITS) / NBLK;
    int u1 = ((b + 1) * NUNITS) / NBLK;
    int tile = u0 / N;
    int i = u0 - tile * N;
    int remaining = u1 - u0;

    const u64 NEG1 = 0xBF800000BF800000ULL;  // {-1.f, -1.f}

    float wacc = 0.f;

    while (remaining > 0) {
        int cnt = min(N - i, remaining);
        remaining -= cnt;

        int jq = c_TA[tile] * 64 + ty * 4;
        int kq = c_TB[tile] * 64 + tx * 4;

        // G microtile (4x4, both sides) in registers as packed pairs
        u64 G2s[4][2], G2t[4][2];
#pragma unroll
        for (int jj = 0; jj < 4; jj++) {
            float4 vs = *reinterpret_cast<const float4*>(&g_Gs[(jq + jj) * N + kq]);
            float4 vt = *reinterpret_cast<const float4*>(&g_Gt[(jq + jj) * N + kq]);
            G2s[jj][0] = pack2(vs.x, vs.y); G2s[jj][1] = pack2(vs.z, vs.w);
            G2t[jj][0] = pack2(vt.x, vt.y); G2t[jj][1] = pack2(vt.z, vt.w);
        }

        float acc0 = 0.f, acc1 = 0.f;

#pragma unroll 2
        for (int s = 0; s < cnt; s++) {
            int base = (i + s) * N;
            float4 pj_s = *reinterpret_cast<const float4*>(&g_ps[base + jq]);
            float4 cj_s = *reinterpret_cast<const float4*>(&g_cps[base + jq]);
            float4 qk_s = *reinterpret_cast<const float4*>(&g_ps[base + kq]);
            float4 nr_s = *reinterpret_cast<const float4*>(&g_nrqs[base + kq]);
            float4 pj_t = *reinterpret_cast<const float4*>(&g_pt[base + jq]);
            float4 cj_t = *reinterpret_cast<const float4*>(&g_cpt[base + jq]);
            float4 qk_t = *reinterpret_cast<const float4*>(&g_pt[base + kq]);
            float4 nr_t = *reinterpret_cast<const float4*>(&g_nrqt[base + kq]);

            u64 q2s[2] = { pack2(qk_s.x, qk_s.y), pack2(qk_s.z, qk_s.w) };
            u64 n2s[2] = { pack2(nr_s.x, nr_s.y), pack2(nr_s.z, nr_s.w) };
            u64 q2t[2] = { pack2(qk_t.x, qk_t.y), pack2(qk_t.z, qk_t.w) };
            u64 n2t[2] = { pack2(nr_t.x, nr_t.y), pack2(nr_t.z, nr_t.w) };

            float pjs_a[4] = {pj_s.x, pj_s.y, pj_s.z, pj_s.w};
            float cjs_a[4] = {cj_s.x, cj_s.y, cj_s.z, cj_s.w};
            float pjt_a[4] = {pj_t.x, pj_t.y, pj_t.z, pj_t.w};
            float cjt_a[4] = {cj_t.x, cj_t.y, cj_t.z, cj_t.w};

#pragma unroll
            for (int jj = 0; jj < 4; jj++) {
                u64 p2s = pack2(pjs_a[jj], pjs_a[jj]);
                u64 c2s = pack2(cjs_a[jj], cjs_a[jj]);
                u64 p2t = pack2(pjt_a[jj], pjt_a[jj]);
                u64 c2t = pack2(cjt_a[jj], cjt_a[jj]);
#pragma unroll
                for (int p = 0; p < 2; p++) {
                    u64 t2s = fma2(p2s, G2s[jj][p], c2s);
                    u64 m2s = mul2(n2s[p], p2s);
                    u64 a2s = fma2(q2s[p], t2s, m2s);
                    u64 t2t = fma2(p2t, G2t[jj][p], c2t);
                    u64 m2t = mul2(n2t[p], p2t);
                    u64 a2t = fma2(q2t[p], t2t, m2t);
                    u64 d2  = fma2(a2t, NEG1, a2s);      // as - at
                    float2 d = unpack2(d2);
                    float x0 = fabsf(d.x), x1 = fabsf(d.y);
                    float y0 = fminf(x0, 1.f), y1 = fminf(x1, 1.f);
                    float t0 = fmaf(y0, -0.5f, x0);
                    float t1 = fmaf(y1, -0.5f, x1);
                    acc0 = fmaf(y0, t0, acc0);
                    acc1 = fmaf(y1, t1, acc1);
                }
            }
        }

        float w = (c_TA[tile] == c_TB[tile]) ? 1.f : 2.f;
        wacc = fmaf(w, acc0 + acc1, wacc);
        tile++;
        i = 0;
    }

    // block reduction
    __shared__ float red[256];
    red[tid] = wacc;
    __syncthreads();
#pragma unroll
    for (int s = 128; s > 0; s >>= 1) {
        if (tid < s) red[tid] += red[tid + s];
        __syncthreads();
    }
    if (tid == 0) {
        atomicAdd(&g_sum, (double)red[0]);
        __threadfence();
        int t = atomicAdd(&g_cnt, 1);
        if (t == NBLK - 1) {
            double v = atomicAdd(&g_sum, 0.0);
            double n3 = (double)N * (double)N * (double)N;
            out[0] = (float)(v / n3);
        }
    }
}

// ---------------------------------------------------------------------------
extern "C" void kernel_launch(void* const* d_in, const int* in_sizes, int n_in,
                              void* d_out, int out_size) {
    const float* student = (const float*)d_in[0];
    const float* teacher = (const float*)d_in[1];
    float* out = (float*)d_out;

    dim3 ggrd(N / 64, N / 32, 2);
    rkd_gram_prep_kernel<<<ggrd, 256>>>(student, teacher);

    rkd_angle_loss_kernel<<<NBLK, 256>>>(out);
}